// round 16
// baseline (speedup 1.0000x reference)
#include <cuda_runtime.h>

#define NN   100000
#define EE   1600000
#define ET   (EE + NN)
#define FIN  64
#define FH   64
#define FOUT 10
#define NEG  0.2f
#define NB_SCAN 196   // ceil(100000/512)
#define NTILES 1563   // ceil(100000/64)

// split point: multiple of 64 (transform tile) and 8 (aggregate block): 49984
#define TILE_A   781            // tiles [0,781)   -> nodes [0,49984)
#define BLK_A    6248           // blocks [0,6248) -> nodes [0,49984)
#define GRID_N   12500          // ceil(NN/8)

// ---------------- device scratch ----------------
__device__ float g_ht[NN * FH];     // layer-1 h
__device__ float g_ht2[NN * FH];    // layer-2 h (separate: enables agg1/t2 overlap)
__device__ float g_feat[NN * FH];
__device__ float g_as[NN],  g_ad[NN];
__device__ float g_as2[NN], g_ad2[NN];
__device__ float g_ht3[NN * FOUT];
__device__ float g_as3[NN], g_ad3[NN];
__device__ int   g_deg[NN];                      // zero at entry; re-zeroed by k_scatter
__device__ int   g_rowptr[NN + 1];
__device__ int   g_cursor[NN];
__device__ int   g_csr[ET];
__device__ unsigned long long g_bstat[NB_SCAN];  // lookback state; reset by k_scatter

// ---------------- f32x2 helpers ----------------
typedef unsigned long long ull;

__device__ __forceinline__ void ffma2(ull& acc, ull ab, ull cd) {
    asm("fma.rn.f32x2 %0, %1, %2, %0;" : "+l"(acc) : "l"(ab), "l"(cd));
}
__device__ __forceinline__ ull pack2(float lo, float hi) {
    ull r; asm("mov.b64 %0, {%1, %2};" : "=l"(r) : "f"(lo), "f"(hi)); return r;
}
__device__ __forceinline__ float2 unpack2(ull v) {
    float lo, hi; asm("mov.b64 {%0, %1}, %2;" : "=f"(lo), "=f"(hi) : "l"(v));
    return make_float2(lo, hi);
}

// ---------------- CSR build ----------------
__global__ void k_count(const int* __restrict__ ei) {
    int i = blockIdx.x * blockDim.x + threadIdx.x;
    if (i < EE) atomicAdd(&g_deg[ei[EE + i]], 1);
}

__global__ void __launch_bounds__(512) k_scan_lb() {
    __shared__ int sh[512];
    __shared__ int s_excl;
    int tid = threadIdx.x;
    int b = blockIdx.x;
    int i = b * 512 + tid;
    int v = (i < NN) ? (g_deg[i] + 1) : 0;   // +1 = self loop
    sh[tid] = v;
    __syncthreads();
    for (int off = 1; off < 512; off <<= 1) {
        int t = (tid >= off) ? sh[tid - off] : 0;
        __syncthreads();
        sh[tid] += t;
        __syncthreads();
    }
    int total = sh[511];

    if (tid == 0) {
        if (b == 0) {
            atomicExch(&g_bstat[0], (2ull << 32) | (unsigned)total);
            s_excl = 0;
        } else {
            atomicExch(&g_bstat[b], (1ull << 32) | (unsigned)total);
            int excl = 0;
            int j = b - 1;
            while (true) {
                ull s;
                do { s = atomicAdd(&g_bstat[j], 0ull); } while ((s >> 32) == 0ull);
                excl += (int)(s & 0xffffffffull);
                if ((s >> 32) == 2ull) break;
                j--;
            }
            atomicExch(&g_bstat[b], (2ull << 32) | (unsigned)(excl + total));
            s_excl = excl;
        }
    }
    __syncthreads();
    int excl = s_excl;
    if (i < NN) {
        int r = excl + sh[tid] - v;
        g_rowptr[i] = r;
        g_cursor[i] = r;
    }
    if (i == NN - 1) g_rowptr[NN] = ET;
}

// scalar scatter (R13-proven); resets g_deg / g_bstat for replay
__global__ void k_scatter(const int* __restrict__ ei) {
    int i = blockIdx.x * blockDim.x + threadIdx.x;
    if (i >= ET) return;
    int s, d;
    if (i < EE) { s = ei[i]; d = ei[EE + i]; }
    else {
        s = i - EE; d = s;
        g_deg[s] = 0;
        if (s < NB_SCAN) g_bstat[s] = 0ull;
    }
    int pos = atomicAdd(&g_cursor[d], 1);
    g_csr[pos] = s;
}

// ---------------- transform 64->64 (R9 config + tile offset) ----------------
// 64-node tile, 128 threads; thread = 4 nodes x 8 cols.
__global__ void __launch_bounds__(128) k_transform64(
                              const float* __restrict__ xin,
                              const float* __restrict__ W,
                              const float* __restrict__ avs,
                              const float* __restrict__ avd,
                              float* __restrict__ hto,
                              float* __restrict__ aso,
                              float* __restrict__ ado,
                              int tileoff) {
    __shared__ float Wsh[64 * 64];
    __shared__ float xs[64][68];
    __shared__ float ash[64], adh[64];

    int tid = threadIdx.x;
    for (int i = tid; i < 64 * 64; i += 128)
        Wsh[i] = W[i];
    if (tid < 64) { ash[tid] = avs[tid]; adh[tid] = avd[tid]; }

    int tilebase = (blockIdx.x + tileoff) * 64;

    for (int i = tid; i < 64 * 16; i += 128) {
        int node = i >> 4;
        int c4 = (i & 15) * 4;
        int gn = tilebase + node;
        float4 v = make_float4(0.f, 0.f, 0.f, 0.f);
        if (gn < NN)
            v = *reinterpret_cast<const float4*>(&xin[gn * 64 + c4]);
        *reinterpret_cast<float4*>(&xs[node][c4]) = v;
    }
    __syncthreads();

    int cg = tid & 7;
    int np = tid >> 3;
    int c0 = cg * 8;
    int nb = np * 4;

    ull acc[16];
#pragma unroll
    for (int i = 0; i < 16; i++) acc[i] = 0ull;

    for (int kt = 0; kt < 64; kt += 4) {
        float xv[4][4];
#pragma unroll
        for (int m = 0; m < 4; m++) {
            float4 t = *reinterpret_cast<const float4*>(&xs[nb + m][kt]);
            xv[m][0] = t.x; xv[m][1] = t.y; xv[m][2] = t.z; xv[m][3] = t.w;
        }
#pragma unroll
        for (int kk = 0; kk < 4; kk++) {
            int k = kt + kk;
            ulonglong2 w01 = *reinterpret_cast<const ulonglong2*>(&Wsh[k * 64 + c0]);
            ulonglong2 w23 = *reinterpret_cast<const ulonglong2*>(&Wsh[k * 64 + c0 + 4]);
#pragma unroll
            for (int m = 0; m < 4; m++) {
                ull xd = pack2(xv[m][kk], xv[m][kk]);
                ffma2(acc[m * 4 + 0], xd, w01.x);
                ffma2(acc[m * 4 + 1], xd, w01.y);
                ffma2(acc[m * 4 + 2], xd, w23.x);
                ffma2(acc[m * 4 + 3], xd, w23.y);
            }
        }
    }

#pragma unroll
    for (int m = 0; m < 4; m++) {
        int n = tilebase + nb + m;
        float2 u0 = unpack2(acc[m * 4 + 0]);
        float2 u1 = unpack2(acc[m * 4 + 1]);
        float2 u2 = unpack2(acc[m * 4 + 2]);
        float2 u3 = unpack2(acc[m * 4 + 3]);

        float ps = u0.x * ash[c0]     + u0.y * ash[c0 + 1] + u1.x * ash[c0 + 2] + u1.y * ash[c0 + 3]
                 + u2.x * ash[c0 + 4] + u2.y * ash[c0 + 5] + u3.x * ash[c0 + 6] + u3.y * ash[c0 + 7];
        float pd = u0.x * adh[c0]     + u0.y * adh[c0 + 1] + u1.x * adh[c0 + 2] + u1.y * adh[c0 + 3]
                 + u2.x * adh[c0 + 4] + u2.y * adh[c0 + 5] + u3.x * adh[c0 + 6] + u3.y * adh[c0 + 7];
#pragma unroll
        for (int off = 4; off > 0; off >>= 1) {
            ps += __shfl_down_sync(0xffffffffu, ps, off, 8);
            pd += __shfl_down_sync(0xffffffffu, pd, off, 8);
        }
        if (n < NN) {
            if (cg == 0) { aso[n] = ps; ado[n] = pd; }
            *reinterpret_cast<float4*>(&hto[n * 64 + c0])     = make_float4(u0.x, u0.y, u1.x, u1.y);
            *reinterpret_cast<float4*>(&hto[n * 64 + c0 + 4]) = make_float4(u2.x, u2.y, u3.x, u3.y);
        }
    }
}

// ---------------- aggregate FO=64 (R13 config + src pointers + block offset) ----------------
template <int FUSE3>
__global__ void __launch_bounds__(256) k_aggregate64(
                              const float* __restrict__ htp,
                              const float* __restrict__ asp,
                              const float* __restrict__ adp,
                              const float* __restrict__ bias,
                              float* __restrict__ outp,
                              const float* __restrict__ W3,
                              const float* __restrict__ a3s,
                              const float* __restrict__ a3d,
                              int blockoff) {
    __shared__ float W3sh[FUSE3 ? 64 * FOUT : 1];
    __shared__ float a3sh[FUSE3 ? FOUT : 1];
    __shared__ float a3dh[FUSE3 ? FOUT : 1];

    int tid = threadIdx.x;
    if (FUSE3) {
        for (int i = tid; i < 64 * FOUT; i += 256) W3sh[i] = W3[i];
        if (tid < FOUT) { a3sh[tid] = a3s[tid]; a3dh[tid] = a3d[tid]; }
        __syncthreads();
    }

    int warp = tid >> 5, lane = tid & 31;
    int n = (blockIdx.x + blockoff) * 8 + warp;
    if (n >= NN) return;

    int r0 = g_rowptr[n];
    int r1 = g_rowptr[n + 1];
    float adn = adp[n];

    int sg = lane >> 3;
    int c8 = (lane & 7) * 8;

    float ssum_l = 0.f;
    ull acc[4] = {0ull, 0ull, 0ull, 0ull};

    for (int base = r0; base < r1; base += 32) {
        int idx = base + lane;
        bool valid = idx < r1;
        int s = valid ? g_csr[idx] : 0;
        float w = 0.f;
        if (valid) {
            float e = asp[s] + adn;
            e = (e > 0.f) ? e : NEG * e;       // leaky_relu
            w = __expf(e);                      // scores O(10): no max shift needed
        }
        ssum_l += w;

        int cnt = min(32, r1 - base);
#pragma unroll
        for (int j = 0; j < 32; j += 4) {
            if (j >= cnt) break;                // warp-uniform early exit
            int jj = j + sg;
            float wj = __shfl_sync(0xffffffffu, w, jj);
            int   sj = __shfl_sync(0xffffffffu, s, jj);
            if (jj < cnt) {
                const ulonglong2* hp = reinterpret_cast<const ulonglong2*>(&htp[sj * 64 + c8]);
                ulonglong2 h0 = hp[0];
                ulonglong2 h1 = hp[1];
                ull wd = pack2(wj, wj);
                ffma2(acc[0], wd, h0.x);
                ffma2(acc[1], wd, h0.y);
                ffma2(acc[2], wd, h1.x);
                ffma2(acc[3], wd, h1.y);
            }
        }
    }

    float ssum = ssum_l;
#pragma unroll
    for (int o = 16; o > 0; o >>= 1)
        ssum += __shfl_xor_sync(0xffffffffu, ssum, o);

    float f[8];
    {
        float2 a = unpack2(acc[0]), b = unpack2(acc[1]);
        float2 c = unpack2(acc[2]), d = unpack2(acc[3]);
        f[0] = a.x; f[1] = a.y; f[2] = b.x; f[3] = b.y;
        f[4] = c.x; f[5] = c.y; f[6] = d.x; f[7] = d.y;
    }
#pragma unroll
    for (int i = 0; i < 8; i++) {
        f[i] += __shfl_xor_sync(0xffffffffu, f[i], 8);
        f[i] += __shfl_xor_sync(0xffffffffu, f[i], 16);
    }

    if (sg == 0) {
        float inv = 1.f / ssum;
        float4 b0 = *reinterpret_cast<const float4*>(&bias[c8]);
        float4 b1 = *reinterpret_cast<const float4*>(&bias[c8 + 4]);
        float vv[8];
        vv[0] = fmaxf(fmaf(f[0], inv, b0.x), 0.f);
        vv[1] = fmaxf(fmaf(f[1], inv, b0.y), 0.f);
        vv[2] = fmaxf(fmaf(f[2], inv, b0.z), 0.f);
        vv[3] = fmaxf(fmaf(f[3], inv, b0.w), 0.f);
        vv[4] = fmaxf(fmaf(f[4], inv, b1.x), 0.f);
        vv[5] = fmaxf(fmaf(f[5], inv, b1.y), 0.f);
        vv[6] = fmaxf(fmaf(f[6], inv, b1.z), 0.f);
        vv[7] = fmaxf(fmaf(f[7], inv, b1.w), 0.f);

        if (!FUSE3) {
            *reinterpret_cast<float4*>(&outp[n * 64 + c8]) =
                make_float4(vv[0], vv[1], vv[2], vv[3]);
            *reinterpret_cast<float4*>(&outp[n * 64 + c8 + 4]) =
                make_float4(vv[4], vv[5], vv[6], vv[7]);
        } else {
            float h3[FOUT];
#pragma unroll
            for (int j = 0; j < FOUT; j++) h3[j] = 0.f;
#pragma unroll
            for (int c = 0; c < 8; c++) {
                float xc = vv[c];
#pragma unroll
                for (int j = 0; j < FOUT; j++)
                    h3[j] = fmaf(xc, W3sh[(c8 + c) * FOUT + j], h3[j]);
            }
#pragma unroll
            for (int off = 4; off > 0; off >>= 1) {
#pragma unroll
                for (int j = 0; j < FOUT; j++)
                    h3[j] += __shfl_xor_sync(0x000000ffu, h3[j], off);
            }
            float as3 = 0.f, ad3 = 0.f;
#pragma unroll
            for (int j = 0; j < FOUT; j++) {
                as3 = fmaf(h3[j], a3sh[j], as3);
                ad3 = fmaf(h3[j], a3dh[j], ad3);
            }
            int fl = lane;               // 0..7
            g_ht3[n * FOUT + fl] = h3[fl];
            if (fl < 2) g_ht3[n * FOUT + 8 + fl] = h3[8 + fl];
            if (fl == 0) { g_as3[n] = as3; g_ad3[n] = ad3; }
        }
    }
}

// ---------------- aggregate FO=10 (final layer, log_softmax) ----------------
__global__ void __launch_bounds__(256) k_aggregate10(
                              const float* __restrict__ bias,
                              float* __restrict__ outp) {
    int tid = threadIdx.x;
    int warp = tid >> 5, lane = tid & 31;
    int n = blockIdx.x * 8 + warp;
    if (n >= NN) return;

    int r0 = g_rowptr[n];
    int r1 = g_rowptr[n + 1];
    float adn = g_ad3[n];

    int hf = lane >> 4;
    int fl = lane & 15;

    float ssum_l = 0.f, acc0 = 0.f;

    for (int base = r0; base < r1; base += 32) {
        int idx = base + lane;
        bool valid = idx < r1;
        int s = valid ? g_csr[idx] : 0;
        float w = 0.f;
        if (valid) {
            float e = g_as3[s] + adn;
            e = (e > 0.f) ? e : NEG * e;
            w = __expf(e);
        }
        ssum_l += w;

        int cnt = min(32, r1 - base);
#pragma unroll
        for (int j = 0; j < 32; j += 2) {
            if (j >= cnt) break;
            int jj = j + hf;
            float wj = __shfl_sync(0xffffffffu, w, jj);
            int   sj = __shfl_sync(0xffffffffu, s, jj);
            if (jj < cnt && fl < FOUT)
                acc0 = fmaf(wj, g_ht3[sj * FOUT + fl], acc0);
        }
    }

    float ssum = ssum_l;
#pragma unroll
    for (int o = 16; o > 0; o >>= 1)
        ssum += __shfl_xor_sync(0xffffffffu, ssum, o);

    acc0 += __shfl_xor_sync(0xffffffffu, acc0, 16);

    float inv = 1.f / ssum;
    float v = (lane < FOUT) ? (acc0 * inv + bias[lane]) : -3.4e38f;
    float mx = v;
#pragma unroll
    for (int o = 16; o > 0; o >>= 1)
        mx = fmaxf(mx, __shfl_xor_sync(0xffffffffu, mx, o));
    float ex = (lane < FOUT) ? __expf(v - mx) : 0.f;
    float se = ex;
#pragma unroll
    for (int o = 16; o > 0; o >>= 1)
        se += __shfl_xor_sync(0xffffffffu, se, o);
    float lse = logf(se) + mx;
    if (lane < FOUT) outp[n * FOUT + lane] = v - lse;
}

// ---------------- launch ----------------
extern "C" void kernel_launch(void* const* d_in, const int* in_sizes, int n_in,
                              void* d_out, int out_size) {
    const float* x   = (const float*)d_in[0];
    const int*   ei  = (const int*)d_in[1];
    const float* W1  = (const float*)d_in[2];
    const float* a1s = (const float*)d_in[3];
    const float* a1d = (const float*)d_in[4];
    const float* b1  = (const float*)d_in[5];
    const float* W2  = (const float*)d_in[6];
    const float* a2s = (const float*)d_in[7];
    const float* a2d = (const float*)d_in[8];
    const float* b2  = (const float*)d_in[9];
    const float* W3  = (const float*)d_in[10];
    const float* a3s = (const float*)d_in[11];
    const float* a3d = (const float*)d_in[12];
    const float* b3  = (const float*)d_in[13];
    float* outp = (float*)d_out;

    float *featp, *ht1p, *ht2p, *as1p, *ad1p, *as2p, *ad2p;
    cudaGetSymbolAddress((void**)&featp, g_feat);
    cudaGetSymbolAddress((void**)&ht1p, g_ht);
    cudaGetSymbolAddress((void**)&ht2p, g_ht2);
    cudaGetSymbolAddress((void**)&as1p, g_as);
    cudaGetSymbolAddress((void**)&ad1p, g_ad);
    cudaGetSymbolAddress((void**)&as2p, g_as2);
    cudaGetSymbolAddress((void**)&ad2p, g_ad2);

    // one-time host-side stream/event objects (no device memory involved).
    static cudaStream_t s2 = nullptr;
    static cudaEvent_t evFork = nullptr, evJoin = nullptr, evA1 = nullptr, evA2 = nullptr, evT2 = nullptr;
    if (s2 == nullptr) {
        cudaStreamCreateWithFlags(&s2, cudaStreamNonBlocking);
        cudaEventCreateWithFlags(&evFork, cudaEventDisableTiming);
        cudaEventCreateWithFlags(&evJoin, cudaEventDisableTiming);
        cudaEventCreateWithFlags(&evA1, cudaEventDisableTiming);
        cudaEventCreateWithFlags(&evA2, cudaEventDisableTiming);
        cudaEventCreateWithFlags(&evT2, cudaEventDisableTiming);
    }

    // ---- phase 1: CSR build (s2) || layer-1 transform (main) ----
    cudaEventRecord(evFork, 0);
    cudaStreamWaitEvent(s2, evFork, 0);

    k_transform64<<<NTILES, 128>>>(x, W1, a1s, a1d, ht1p, as1p, ad1p, 0);

    k_count<<<(EE + 255) / 256, 256, 0, s2>>>(ei);
    k_scan_lb<<<NB_SCAN, 512, 0, s2>>>();
    k_scatter<<<(ET + 255) / 256, 256, 0, s2>>>(ei);

    cudaEventRecord(evJoin, s2);
    cudaStreamWaitEvent(0, evJoin, 0);

    // ---- phase 2: agg1 split || transform-2 pipelined ----
    // agg1_A (nodes [0,49984)) then agg1_B on main; t2 halves trail on s2.
    k_aggregate64<0><<<BLK_A, 256>>>(ht1p, as1p, ad1p, b1, featp,
                                     nullptr, nullptr, nullptr, 0);
    cudaEventRecord(evA1, 0);
    k_aggregate64<0><<<GRID_N - BLK_A, 256>>>(ht1p, as1p, ad1p, b1, featp,
                                              nullptr, nullptr, nullptr, BLK_A);
    cudaEventRecord(evA2, 0);

    cudaStreamWaitEvent(s2, evA1, 0);
    k_transform64<<<TILE_A, 128, 0, s2>>>(featp, W2, a2s, a2d, ht2p, as2p, ad2p, 0);
    cudaStreamWaitEvent(s2, evA2, 0);
    k_transform64<<<NTILES - TILE_A, 128, 0, s2>>>(featp, W2, a2s, a2d, ht2p, as2p, ad2p, TILE_A);

    cudaEventRecord(evT2, s2);
    cudaStreamWaitEvent(0, evT2, 0);

    // ---- phase 3: agg2 (+fused t3) then agg3 ----
    k_aggregate64<1><<<GRID_N, 256>>>(ht2p, as2p, ad2p, b2, nullptr,
                                      W3, a3s, a3d, 0);
    k_aggregate10<<<GRID_N, 256>>>(b3, outp);
}

// round 17
// speedup vs baseline: 1.0318x; 1.0318x over previous
#include <cuda_runtime.h>

#define NN   100000
#define EE   1600000
#define ET   (EE + NN)
#define FIN  64
#define FH   64
#define FOUT 10
#define NEG  0.2f
#define NB_SCAN 196   // ceil(100000/512)
#define NTILES 1563   // ceil(100000/64)

// ---------------- device scratch ----------------
__device__ float g_ht[NN * FH];
__device__ float g_feat[NN * FH];
__device__ float g_as[NN];
__device__ float g_ad[NN];
__device__ float g_ht3[NN * FOUT];
__device__ float g_as3[NN];
__device__ float g_ad3[NN];
__device__ int   g_deg[NN];                      // zero at entry (zero-init; re-zeroed by k_scatter)
__device__ int   g_rowptr[NN + 1];
__device__ int   g_cursor[NN];
__device__ int   g_csr[ET];
__device__ unsigned long long g_bstat[NB_SCAN];  // lookback scan state; reset by k_scatter

// ---------------- f32x2 helpers ----------------
typedef unsigned long long ull;

__device__ __forceinline__ void ffma2(ull& acc, ull ab, ull cd) {
    asm("fma.rn.f32x2 %0, %1, %2, %0;" : "+l"(acc) : "l"(ab), "l"(cd));
}
__device__ __forceinline__ ull pack2(float lo, float hi) {
    ull r; asm("mov.b64 %0, {%1, %2};" : "=l"(r) : "f"(lo), "f"(hi)); return r;
}
__device__ __forceinline__ float2 unpack2(ull v) {
    float lo, hi; asm("mov.b64 {%0, %1}, %2;" : "=f"(lo), "=f"(hi) : "l"(v));
    return make_float2(lo, hi);
}

// ---------------- CSR build ----------------
__global__ void k_count(const int* __restrict__ ei) {
    int i = blockIdx.x * blockDim.x + threadIdx.x;
    if (i < EE) atomicAdd(&g_deg[ei[EE + i]], 1);
}

// single-pass scan of (deg[i]+1) with decoupled lookback; writes rowptr & cursor
__global__ void __launch_bounds__(512) k_scan_lb() {
    __shared__ int sh[512];
    __shared__ int s_excl;
    int tid = threadIdx.x;
    int b = blockIdx.x;
    int i = b * 512 + tid;
    int v = (i < NN) ? (g_deg[i] + 1) : 0;   // +1 = self loop
    sh[tid] = v;
    __syncthreads();
    for (int off = 1; off < 512; off <<= 1) {
        int t = (tid >= off) ? sh[tid - off] : 0;
        __syncthreads();
        sh[tid] += t;
        __syncthreads();
    }
    int total = sh[511];

    if (tid == 0) {
        if (b == 0) {
            atomicExch(&g_bstat[0], (2ull << 32) | (unsigned)total);
            s_excl = 0;
        } else {
            atomicExch(&g_bstat[b], (1ull << 32) | (unsigned)total);
            int excl = 0;
            int j = b - 1;
            while (true) {
                ull s;
                do { s = atomicAdd(&g_bstat[j], 0ull); } while ((s >> 32) == 0ull);
                excl += (int)(s & 0xffffffffull);
                if ((s >> 32) == 2ull) break;
                j--;
            }
            atomicExch(&g_bstat[b], (2ull << 32) | (unsigned)(excl + total));
            s_excl = excl;
        }
    }
    __syncthreads();
    int excl = s_excl;
    if (i < NN) {
        int r = excl + sh[tid] - v;     // exclusive global prefix
        g_rowptr[i] = r;
        g_cursor[i] = r;
    }
    if (i == NN - 1) g_rowptr[NN] = ET;
}

// scatter edges + self loops; resets g_deg and g_bstat for the next replay
__global__ void k_scatter(const int* __restrict__ ei) {
    int i = blockIdx.x * blockDim.x + threadIdx.x;
    if (i >= ET) return;
    int s, d;
    if (i < EE) { s = ei[i]; d = ei[EE + i]; }
    else {
        s = i - EE; d = s;
        g_deg[s] = 0;                               // replay-safe
        if (s < NB_SCAN) g_bstat[s] = 0ull;         // replay-safe
    }
    int pos = atomicAdd(&g_cursor[d], 1);
    g_csr[pos] = s;
}

// ---------------- transform 64->64 (R9 proven config; float4 W fill) ----------------
// 64-node tile, 128 threads; thread = 4 nodes x 8 cols.
__global__ void __launch_bounds__(128) k_transform64(
                              const float* __restrict__ xin,
                              const float* __restrict__ W,
                              const float* __restrict__ avs,
                              const float* __restrict__ avd) {
    __shared__ float Wsh[64 * 64];
    __shared__ float xs[64][68];        // padded rows -> conflict-free
    __shared__ float ash[64], adh[64];

    int tid = threadIdx.x;
    // W fill: 1024 float4 (vs 4096 scalar) — fewer issue slots in prologue
    for (int i = tid; i < 64 * 16; i += 128)
        reinterpret_cast<float4*>(Wsh)[i] = reinterpret_cast<const float4*>(W)[i];
    if (tid < 64) { ash[tid] = avs[tid]; adh[tid] = avd[tid]; }

    int tilebase = blockIdx.x * 64;

    for (int i = tid; i < 64 * 16; i += 128) {
        int node = i >> 4;
        int c4 = (i & 15) * 4;
        int gn = tilebase + node;
        float4 v = make_float4(0.f, 0.f, 0.f, 0.f);
        if (gn < NN)
            v = *reinterpret_cast<const float4*>(&xin[gn * 64 + c4]);
        *reinterpret_cast<float4*>(&xs[node][c4]) = v;
    }
    __syncthreads();

    int cg = tid & 7;          // col group
    int np = tid >> 3;         // node quad 0..15
    int c0 = cg * 8;
    int nb = np * 4;

    ull acc[16];
#pragma unroll
    for (int i = 0; i < 16; i++) acc[i] = 0ull;

    for (int kt = 0; kt < 64; kt += 4) {
        float xv[4][4];
#pragma unroll
        for (int m = 0; m < 4; m++) {
            float4 t = *reinterpret_cast<const float4*>(&xs[nb + m][kt]);
            xv[m][0] = t.x; xv[m][1] = t.y; xv[m][2] = t.z; xv[m][3] = t.w;
        }
#pragma unroll
        for (int kk = 0; kk < 4; kk++) {
            int k = kt + kk;
            ulonglong2 w01 = *reinterpret_cast<const ulonglong2*>(&Wsh[k * 64 + c0]);
            ulonglong2 w23 = *reinterpret_cast<const ulonglong2*>(&Wsh[k * 64 + c0 + 4]);
#pragma unroll
            for (int m = 0; m < 4; m++) {
                ull xd = pack2(xv[m][kk], xv[m][kk]);
                ffma2(acc[m * 4 + 0], xd, w01.x);
                ffma2(acc[m * 4 + 1], xd, w01.y);
                ffma2(acc[m * 4 + 2], xd, w23.x);
                ffma2(acc[m * 4 + 3], xd, w23.y);
            }
        }
    }

#pragma unroll
    for (int m = 0; m < 4; m++) {
        int n = tilebase + nb + m;
        float2 u0 = unpack2(acc[m * 4 + 0]);
        float2 u1 = unpack2(acc[m * 4 + 1]);
        float2 u2 = unpack2(acc[m * 4 + 2]);
        float2 u3 = unpack2(acc[m * 4 + 3]);

        float ps = u0.x * ash[c0]     + u0.y * ash[c0 + 1] + u1.x * ash[c0 + 2] + u1.y * ash[c0 + 3]
                 + u2.x * ash[c0 + 4] + u2.y * ash[c0 + 5] + u3.x * ash[c0 + 6] + u3.y * ash[c0 + 7];
        float pd = u0.x * adh[c0]     + u0.y * adh[c0 + 1] + u1.x * adh[c0 + 2] + u1.y * adh[c0 + 3]
                 + u2.x * adh[c0 + 4] + u2.y * adh[c0 + 5] + u3.x * adh[c0 + 6] + u3.y * adh[c0 + 7];
#pragma unroll
        for (int off = 4; off > 0; off >>= 1) {
            ps += __shfl_down_sync(0xffffffffu, ps, off, 8);
            pd += __shfl_down_sync(0xffffffffu, pd, off, 8);
        }
        if (n < NN) {
            if (cg == 0) { g_as[n] = ps; g_ad[n] = pd; }
            *reinterpret_cast<float4*>(&g_ht[n * 64 + c0])     = make_float4(u0.x, u0.y, u1.x, u1.y);
            *reinterpret_cast<float4*>(&g_ht[n * 64 + c0 + 4]) = make_float4(u2.x, u2.y, u3.x, u3.y);
        }
    }
}

// ---------------- aggregate FO=64 (R13 proven config) ----------------
// quarter-warp: sg = lane>>3 handles edges j+sg, c8 = (lane&7)*8 owns 8 cols.
// FUSE3 = 1: fuse layer-3 transform; outputs to DISJOINT buffers g_ht3/g_as3/g_ad3.
template <int FUSE3>
__global__ void __launch_bounds__(256) k_aggregate64(
                              const float* __restrict__ bias,
                              float* __restrict__ outp,
                              const float* __restrict__ W3,
                              const float* __restrict__ a3s,
                              const float* __restrict__ a3d) {
    __shared__ float W3sh[FUSE3 ? 64 * FOUT : 1];
    __shared__ float a3sh[FUSE3 ? FOUT : 1];
    __shared__ float a3dh[FUSE3 ? FOUT : 1];

    int tid = threadIdx.x;
    if (FUSE3) {
        for (int i = tid; i < 64 * FOUT; i += 256) W3sh[i] = W3[i];
        if (tid < FOUT) { a3sh[tid] = a3s[tid]; a3dh[tid] = a3d[tid]; }
        __syncthreads();
    }

    int warp = tid >> 5, lane = tid & 31;
    int n = blockIdx.x * 8 + warp;
    if (n >= NN) return;

    int r0 = g_rowptr[n];
    int r1 = g_rowptr[n + 1];
    float adn = g_ad[n];

    int sg = lane >> 3;
    int c8 = (lane & 7) * 8;

    float ssum_l = 0.f;
    ull acc[4] = {0ull, 0ull, 0ull, 0ull};

    for (int base = r0; base < r1; base += 32) {
        int idx = base + lane;
        bool valid = idx < r1;
        int s = valid ? g_csr[idx] : 0;
        float w = 0.f;
        if (valid) {
            float e = g_as[s] + adn;
            e = (e > 0.f) ? e : NEG * e;       // leaky_relu
            w = __expf(e);                      // scores O(10): no max shift needed
        }
        ssum_l += w;

        int cnt = min(32, r1 - base);
#pragma unroll
        for (int j = 0; j < 32; j += 4) {
            if (j >= cnt) break;                // warp-uniform early exit
            int jj = j + sg;
            float wj = __shfl_sync(0xffffffffu, w, jj);
            int   sj = __shfl_sync(0xffffffffu, s, jj);
            if (jj < cnt) {
                const ulonglong2* hp = reinterpret_cast<const ulonglong2*>(&g_ht[sj * 64 + c8]);
                ulonglong2 h0 = hp[0];
                ulonglong2 h1 = hp[1];
                ull wd = pack2(wj, wj);
                ffma2(acc[0], wd, h0.x);
                ffma2(acc[1], wd, h0.y);
                ffma2(acc[2], wd, h1.x);
                ffma2(acc[3], wd, h1.y);
            }
        }
    }

    float ssum = ssum_l;
#pragma unroll
    for (int o = 16; o > 0; o >>= 1)
        ssum += __shfl_xor_sync(0xffffffffu, ssum, o);

    float f[8];
    {
        float2 a = unpack2(acc[0]), b = unpack2(acc[1]);
        float2 c = unpack2(acc[2]), d = unpack2(acc[3]);
        f[0] = a.x; f[1] = a.y; f[2] = b.x; f[3] = b.y;
        f[4] = c.x; f[5] = c.y; f[6] = d.x; f[7] = d.y;
    }
#pragma unroll
    for (int i = 0; i < 8; i++) {
        f[i] += __shfl_xor_sync(0xffffffffu, f[i], 8);
        f[i] += __shfl_xor_sync(0xffffffffu, f[i], 16);
    }

    if (sg == 0) {
        float inv = 1.f / ssum;
        float4 b0 = *reinterpret_cast<const float4*>(&bias[c8]);
        float4 b1 = *reinterpret_cast<const float4*>(&bias[c8 + 4]);
        float vv[8];
        vv[0] = fmaxf(fmaf(f[0], inv, b0.x), 0.f);
        vv[1] = fmaxf(fmaf(f[1], inv, b0.y), 0.f);
        vv[2] = fmaxf(fmaf(f[2], inv, b0.z), 0.f);
        vv[3] = fmaxf(fmaf(f[3], inv, b0.w), 0.f);
        vv[4] = fmaxf(fmaf(f[4], inv, b1.x), 0.f);
        vv[5] = fmaxf(fmaf(f[5], inv, b1.y), 0.f);
        vv[6] = fmaxf(fmaf(f[6], inv, b1.z), 0.f);
        vv[7] = fmaxf(fmaf(f[7], inv, b1.w), 0.f);

        if (!FUSE3) {
            *reinterpret_cast<float4*>(&outp[n * 64 + c8]) =
                make_float4(vv[0], vv[1], vv[2], vv[3]);
            *reinterpret_cast<float4*>(&outp[n * 64 + c8 + 4]) =
                make_float4(vv[4], vv[5], vv[6], vv[7]);
        } else {
            float h3[FOUT];
#pragma unroll
            for (int j = 0; j < FOUT; j++) h3[j] = 0.f;
#pragma unroll
            for (int c = 0; c < 8; c++) {
                float xc = vv[c];
#pragma unroll
                for (int j = 0; j < FOUT; j++)
                    h3[j] = fmaf(xc, W3sh[(c8 + c) * FOUT + j], h3[j]);
            }
#pragma unroll
            for (int off = 4; off > 0; off >>= 1) {
#pragma unroll
                for (int j = 0; j < FOUT; j++)
                    h3[j] += __shfl_xor_sync(0x000000ffu, h3[j], off);
            }
            float as3 = 0.f, ad3 = 0.f;
#pragma unroll
            for (int j = 0; j < FOUT; j++) {
                as3 = fmaf(h3[j], a3sh[j], as3);
                ad3 = fmaf(h3[j], a3dh[j], ad3);
            }
            int fl = lane;               // 0..7
            g_ht3[n * FOUT + fl] = h3[fl];
            if (fl < 2) g_ht3[n * FOUT + 8 + fl] = h3[8 + fl];
            if (fl == 0) { g_as3[n] = as3; g_ad3[n] = ad3; }
        }
    }
}

// ---------------- aggregate FO=10 (final layer, log_softmax) ----------------
__global__ void __launch_bounds__(256) k_aggregate10(
                              const float* __restrict__ bias,
                              float* __restrict__ outp) {
    int tid = threadIdx.x;
    int warp = tid >> 5, lane = tid & 31;
    int n = blockIdx.x * 8 + warp;
    if (n >= NN) return;

    int r0 = g_rowptr[n];
    int r1 = g_rowptr[n + 1];
    float adn = g_ad3[n];

    int hf = lane >> 4;
    int fl = lane & 15;

    float ssum_l = 0.f, acc0 = 0.f;

    for (int base = r0; base < r1; base += 32) {
        int idx = base + lane;
        bool valid = idx < r1;
        int s = valid ? g_csr[idx] : 0;
        float w = 0.f;
        if (valid) {
            float e = g_as3[s] + adn;
            e = (e > 0.f) ? e : NEG * e;
            w = __expf(e);
        }
        ssum_l += w;

        int cnt = min(32, r1 - base);
#pragma unroll
        for (int j = 0; j < 32; j += 2) {
            if (j >= cnt) break;
            int jj = j + hf;
            float wj = __shfl_sync(0xffffffffu, w, jj);
            int   sj = __shfl_sync(0xffffffffu, s, jj);
            if (jj < cnt && fl < FOUT)
                acc0 = fmaf(wj, g_ht3[sj * FOUT + fl], acc0);
        }
    }

    float ssum = ssum_l;
#pragma unroll
    for (int o = 16; o > 0; o >>= 1)
        ssum += __shfl_xor_sync(0xffffffffu, ssum, o);

    acc0 += __shfl_xor_sync(0xffffffffu, acc0, 16);

    float inv = 1.f / ssum;
    float v = (lane < FOUT) ? (acc0 * inv + bias[lane]) : -3.4e38f;
    float mx = v;
#pragma unroll
    for (int o = 16; o > 0; o >>= 1)
        mx = fmaxf(mx, __shfl_xor_sync(0xffffffffu, mx, o));
    float ex = (lane < FOUT) ? __expf(v - mx) : 0.f;
    float se = ex;
#pragma unroll
    for (int o = 16; o > 0; o >>= 1)
        se += __shfl_xor_sync(0xffffffffu, se, o);
    float lse = logf(se) + mx;
    if (lane < FOUT) outp[n * FOUT + lane] = v - lse;
}

// ---------------- launch ----------------
extern "C" void kernel_launch(void* const* d_in, const int* in_sizes, int n_in,
                              void* d_out, int out_size) {
    const float* x   = (const float*)d_in[0];
    const int*   ei  = (const int*)d_in[1];
    const float* W1  = (const float*)d_in[2];
    const float* a1s = (const float*)d_in[3];
    const float* a1d = (const float*)d_in[4];
    const float* b1  = (const float*)d_in[5];
    const float* W2  = (const float*)d_in[6];
    const float* a2s = (const float*)d_in[7];
    const float* a2d = (const float*)d_in[8];
    const float* b2  = (const float*)d_in[9];
    const float* W3  = (const float*)d_in[10];
    const float* a3s = (const float*)d_in[11];
    const float* a3d = (const float*)d_in[12];
    const float* b3  = (const float*)d_in[13];
    float* outp = (float*)d_out;

    float* featp = nullptr;
    cudaGetSymbolAddress((void**)&featp, g_feat);

    const int gridN = (NN + 7) / 8;

    // one-time host-side stream/event objects (no device memory involved).
    static cudaStream_t s2 = nullptr;
    static cudaEvent_t evFork = nullptr, evJoin = nullptr;
    if (s2 == nullptr) {
        cudaStreamCreateWithFlags(&s2, cudaStreamNonBlocking);
        cudaEventCreateWithFlags(&evFork, cudaEventDisableTiming);
        cudaEventCreateWithFlags(&evJoin, cudaEventDisableTiming);
    }

    // ---- fork: CSR build on s2, layer-1 transform on main stream ----
    cudaEventRecord(evFork, 0);
    cudaStreamWaitEvent(s2, evFork, 0);

    // main stream: layer-1 transform (independent of CSR)
    k_transform64<<<NTILES, 128>>>(x, W1, a1s, a1d);

    // s2: CSR build chain
    k_count<<<(EE + 255) / 256, 256, 0, s2>>>(ei);
    k_scan_lb<<<NB_SCAN, 512, 0, s2>>>();
    k_scatter<<<(ET + 255) / 256, 256, 0, s2>>>(ei);

    // ---- join ----
    cudaEventRecord(evJoin, s2);
    cudaStreamWaitEvent(0, evJoin, 0);

    // layer-1 aggregate -> feat
    k_aggregate64<0><<<gridN, 256>>>(b1, featp, nullptr, nullptr, nullptr);
    // layer-2 transform
    k_transform64<<<NTILES, 128>>>(featp, W2, a2s, a2d);
    // layer-2 aggregate + fused layer-3 transform
    k_aggregate64<1><<<gridN, 256>>>(b2, nullptr, W3, a3s, a3d);
    // layer-3 aggregate + log_softmax -> out
    k_aggregate10<<<gridN, 256>>>(b3, outp);
}